// round 1
// baseline (speedup 1.0000x reference)
#include <cuda_runtime.h>
#include <cstdint>

#define CIN   32
#define COUT  64
#define TT    8
#define DDIM  32
#define HDIM  64
#define WDIM  64
#define BDIM  4

// shared memory layout (floats)
#define XS_SIZE   (CIN * 9 * 68)        // 19584: x tile, row stride 68 (16B aligned)
#define WS_OFF    XS_SIZE
#define WS_SIZE   (256 * 64)            // 16384: weight transposed k-major, swizzled
#define TAP_OFF   (WS_OFF + WS_SIZE)
#define TAP_SIZE  (256 * 68)            // 17408: tap[k][p], row stride 68
#define SMEM_FLOATS (TAP_OFF + TAP_SIZE)
#define SMEM_BYTES  (SMEM_FLOATS * 4)   // 213504 B

__device__ __forceinline__ uint64_t dup_f32x2(float v) {
    uint64_t r;
    asm("mov.b64 %0, {%1, %1};" : "=l"(r) : "f"(v));
    return r;
}
__device__ __forceinline__ void ffma2(uint64_t& d, uint64_t a, uint64_t b) {
    asm("fma.rn.f32x2 %0, %1, %2, %0;" : "+l"(d) : "l"(a), "l"(b));
}
__device__ __forceinline__ void unpack_f32x2(uint64_t v, float& lo, float& hi) {
    asm("mov.b64 {%0, %1}, %2;" : "=f"(lo), "=f"(hi) : "l"(v));
}

__global__ __launch_bounds__(256, 1)
void stencilconv3d_kernel(const float* __restrict__ x,
                          const float* __restrict__ stencils,
                          const float* __restrict__ weight,
                          const float* __restrict__ bias,
                          float* __restrict__ out) {
    extern __shared__ float sm[];
    float* xs  = sm;
    float* ws  = sm + WS_OFF;
    float* tap = sm + TAP_OFF;

    const int h0  = blockIdx.x;   // 0..63
    const int d0  = blockIdx.y;   // 0..31
    const int b   = blockIdx.z;   // 0..3
    const int tid = threadIdx.x;

    // ------- load x tile (32 ch, 3d x 3h x 66w window, zero-padded) -------
    const float* xb = x + (size_t)b * CIN * DDIM * HDIM * WDIM;
    for (int idx = tid; idx < XS_SIZE; idx += 256) {
        int wx  = idx % 68;
        int row = idx / 68;
        int c   = row / 9;
        int rr  = row - c * 9;
        int dz  = rr / 3;
        int hy  = rr - dz * 3;
        int dg  = d0 + dz - 1;
        int hg  = h0 + hy - 1;
        int wg  = wx - 1;
        float v = 0.f;
        if (wx < 66 && (unsigned)dg < DDIM && (unsigned)hg < HDIM && (unsigned)wg < WDIM)
            v = xb[((c * DDIM + dg) * HDIM + hg) * WDIM + wg];
        xs[idx] = v;
    }

    // ------- load weight, transposed to k-major with 4-float group swizzle -------
    // ws logical [k=c*8+t][o], stored at k*64 + ((o>>2)^(k&15))*4 + (o&3)
    for (int idx = tid; idx < WS_SIZE; idx += 256) {
        int k = idx & 255;
        int o = idx >> 8;
        float v = weight[o * 256 + k];
        int sw = k * 64 + (((o >> 2) ^ (k & 15)) << 2) + (o & 3);
        ws[sw] = v;
    }

    // ------- stencil for this thread's tap into registers -------
    const int t      = tid & 7;
    const int pg     = (tid >> 3) & 15;
    const int ch     = tid >> 7;           // c-half: 0 or 1
    const int p_base = pg << 2;            // 4 consecutive w points

    float st[27];
    const float* sb = stencils + ((size_t)b * TT + t) * 27;
    #pragma unroll
    for (int j = 0; j < 27; j++) st[j] = sb[j];

    __syncthreads();

    // ------- Phase A: taps for 16 channels x 4 points (t fixed per thread) -------
    #pragma unroll 2
    for (int ci = 0; ci < 16; ci++) {
        int c = ch * 16 + ci;
        float win[9][6];
        #pragma unroll
        for (int r = 0; r < 9; r++) {
            const float* xr = &xs[(c * 9 + r) * 68 + p_base];
            float4 a  = *(const float4*)xr;
            float2 b2 = *(const float2*)(xr + 4);
            win[r][0] = a.x;  win[r][1] = a.y;  win[r][2] = a.z;
            win[r][3] = a.w;  win[r][4] = b2.x; win[r][5] = b2.y;
        }
        float a0 = 0.f, a1 = 0.f, a2 = 0.f, a3 = 0.f;
        #pragma unroll
        for (int r = 0; r < 9; r++) {
            #pragma unroll
            for (int wxo = 0; wxo < 3; wxo++) {
                float s = st[r * 3 + wxo];
                a0 += s * win[r][wxo + 0];
                a1 += s * win[r][wxo + 1];
                a2 += s * win[r][wxo + 2];
                a3 += s * win[r][wxo + 3];
            }
        }
        *(float4*)&tap[(c * 8 + t) * 68 + p_base] = make_float4(a0, a1, a2, a3);
    }

    __syncthreads();

    // ------- Phase B: y[64x64] = W[64x256] * tap[256x64], FFMA2 micro-tiles -------
    const int og  = tid >> 4;      // 0..15 -> o group of 4
    const int pgl = tid & 15;      // 0..15 -> p group of 4
    const int o_base = og << 2;
    const int pb     = pgl << 2;

    uint64_t acc[4][2];
    #pragma unroll
    for (int i = 0; i < 4; i++) {
        acc[i][0] = 0ull; acc[i][1] = 0ull;
    }

    #pragma unroll 4
    for (int k = 0; k < 256; k++) {
        float4 wv = *(const float4*)&ws[k * 64 + ((og ^ (k & 15)) << 2)];
        const uint64_t* tp = (const uint64_t*)&tap[k * 68 + pb];
        uint64_t b0 = tp[0];
        uint64_t b1 = tp[1];
        uint64_t aw0 = dup_f32x2(wv.x);
        uint64_t aw1 = dup_f32x2(wv.y);
        uint64_t aw2 = dup_f32x2(wv.z);
        uint64_t aw3 = dup_f32x2(wv.w);
        ffma2(acc[0][0], aw0, b0); ffma2(acc[0][1], aw0, b1);
        ffma2(acc[1][0], aw1, b0); ffma2(acc[1][1], aw1, b1);
        ffma2(acc[2][0], aw2, b0); ffma2(acc[2][1], aw2, b1);
        ffma2(acc[3][0], aw3, b0); ffma2(acc[3][1], aw3, b1);
    }

    // ------- epilogue: + bias, store float4 along w -------
    #pragma unroll
    for (int i = 0; i < 4; i++) {
        int o = o_base + i;
        float bv = __ldg(&bias[o]);
        float p0, p1, p2, p3;
        unpack_f32x2(acc[i][0], p0, p1);
        unpack_f32x2(acc[i][1], p2, p3);
        float4 r = make_float4(p0 + bv, p1 + bv, p2 + bv, p3 + bv);
        size_t off = (((size_t)b * COUT + o) * DDIM + d0) * (HDIM * WDIM)
                   + (size_t)h0 * WDIM + pb;
        *(float4*)&out[off] = r;
    }
}

extern "C" void kernel_launch(void* const* d_in, const int* in_sizes, int n_in,
                              void* d_out, int out_size) {
    const float* x        = (const float*)d_in[0];
    const float* stencils = (const float*)d_in[1];
    const float* weight   = (const float*)d_in[2];
    const float* bias     = (const float*)d_in[3];
    float* out = (float*)d_out;

    cudaFuncSetAttribute(stencilconv3d_kernel,
                         cudaFuncAttributeMaxDynamicSharedMemorySize, SMEM_BYTES);
    dim3 grid(HDIM, DDIM, BDIM);   // 64 x 32 x 4 = 8192 blocks
    stencilconv3d_kernel<<<grid, 256, SMEM_BYTES>>>(x, stencils, weight, bias, out);
}

// round 2
// speedup vs baseline: 1.1484x; 1.1484x over previous
#include <cuda_runtime.h>
#include <cstdint>

#define CIN   32
#define COUT  64
#define TT    8
#define DDIM  32
#define HDIM  64
#define WDIM  64
#define BDIM  4

// shared memory layout (float offsets)
#define XS_OFF    0
#define XS_SIZE   (CIN * 9 * 68)          // 19584
#define WS_OFF    (XS_OFF + XS_SIZE)      // 19584
#define WS_SIZE   (256 * 66)              // 16896 (stride 66: conflict-free strided STS, 8B-aligned rows)
#define TAP_OFF   (WS_OFF + WS_SIZE)      // 36480
#define TAP_SIZE  (256 * 68)              // 17408
#define SD_OFF    (TAP_OFF + TAP_SIZE)    // 53888 (even -> 8B aligned)
#define SD_SIZE   (TT * 27 * 2)           // 432 (stencils pre-duplicated as f32x2)
#define SMEM_FLOATS (SD_OFF + SD_SIZE)    // 54320
#define SMEM_BYTES  (SMEM_FLOATS * 4)     // 217280

__device__ __forceinline__ uint64_t dup_f32x2(float v) {
    uint64_t r;
    asm("mov.b64 %0, {%1, %1};" : "=l"(r) : "f"(v));
    return r;
}
__device__ __forceinline__ uint64_t pack_f32x2(float a, float b) {
    uint64_t r;
    asm("mov.b64 %0, {%1, %2};" : "=l"(r) : "f"(a), "f"(b));
    return r;
}
__device__ __forceinline__ void ffma2(uint64_t& d, uint64_t a, uint64_t b) {
    asm("fma.rn.f32x2 %0, %1, %2, %0;" : "+l"(d) : "l"(a), "l"(b));
}
__device__ __forceinline__ void unpack_f32x2(uint64_t v, float& lo, float& hi) {
    asm("mov.b64 {%0, %1}, %2;" : "=f"(lo), "=f"(hi) : "l"(v));
}

__global__ __launch_bounds__(512, 1)
void stencilconv3d_kernel(const float* __restrict__ x,
                          const float* __restrict__ stencils,
                          const float* __restrict__ weight,
                          const float* __restrict__ bias,
                          float* __restrict__ out) {
    extern __shared__ float sm[];
    float* xs  = sm + XS_OFF;
    float* ws  = sm + WS_OFF;
    float* tap = sm + TAP_OFF;
    uint64_t* sd = (uint64_t*)(sm + SD_OFF);

    const int h0  = blockIdx.x;   // 0..63
    const int d0  = blockIdx.y;   // 0..31
    const int b   = blockIdx.z;   // 0..3
    const int tid = threadIdx.x;

    // ---------- load x tile: 32c x (3d x 3h) x 66w window, zero-padded, stride 68 ----------
    const float* xb = x + (size_t)b * CIN * DDIM * HDIM * WDIM;
    for (int idx = tid; idx < XS_SIZE; idx += 512) {
        int wx  = idx % 68;
        int row = idx / 68;
        int c   = row / 9;
        int rr  = row - c * 9;
        int dz  = rr / 3;
        int hy  = rr - dz * 3;
        int dg  = d0 + dz - 1;
        int hg  = h0 + hy - 1;
        int wg  = wx - 1;
        float v = 0.f;
        if (wx < 66 && (unsigned)dg < DDIM && (unsigned)hg < HDIM && (unsigned)wg < WDIM)
            v = xb[((c * DDIM + dg) * HDIM + hg) * WDIM + wg];
        xs[idx] = v;
    }

    // ---------- load weight transposed: ws[k*66 + o] = weight[o*256 + k] ----------
    // coalesced global read; strided STS (stride 66 -> banks step 2, <=2-way)
    for (int idx = tid; idx < COUT * 256; idx += 512) {
        int o = idx >> 8;
        int k = idx & 255;
        ws[k * 66 + o] = weight[idx];
    }

    // ---------- load stencils pre-duplicated: sd[t*27+s] = {v,v} ----------
    if (tid < TT * 27) {
        float v = stencils[(size_t)b * TT * 27 + tid];
        sd[tid] = dup_f32x2(v);
    }

    __syncthreads();

    // ---------- Phase A: thread = (c, 4-point group); all 8 taps per thread ----------
    {
        const int c  = tid >> 4;          // 0..31
        const int pb = (tid & 15) << 2;   // 0..60

        uint64_t acc[TT][2];
        #pragma unroll
        for (int t = 0; t < TT; t++) { acc[t][0] = 0ull; acc[t][1] = 0ull; }

        #pragma unroll 3
        for (int r = 0; r < 9; r++) {
            const float* xr = &xs[(c * 9 + r) * 68 + pb];
            float4 a4 = *(const float4*)xr;           // w0..w3
            float2 b2 = *(const float2*)(xr + 4);     // w4,w5
            uint64_t A0 = pack_f32x2(a4.x, a4.y);     // {w0,w1}
            uint64_t A1 = pack_f32x2(a4.z, a4.w);     // {w2,w3}
            uint64_t B0 = pack_f32x2(a4.y, a4.z);     // {w1,w2}
            uint64_t B1 = pack_f32x2(a4.w, b2.x);     // {w3,w4}
            uint64_t C1 = pack_f32x2(b2.x, b2.y);     // {w4,w5}
            const uint64_t* sr = &sd[r * 3];
            #pragma unroll
            for (int t = 0; t < TT; t++) {
                uint64_t s0 = sr[t * 27 + 0];
                uint64_t s1 = sr[t * 27 + 1];
                uint64_t s2 = sr[t * 27 + 2];
                ffma2(acc[t][0], s0, A0);  ffma2(acc[t][1], s0, A1);
                ffma2(acc[t][0], s1, B0);  ffma2(acc[t][1], s1, B1);
                ffma2(acc[t][0], s2, A1);  ffma2(acc[t][1], s2, C1);
            }
        }

        #pragma unroll
        for (int t = 0; t < TT; t++) {
            float p0, p1, p2, p3;
            unpack_f32x2(acc[t][0], p0, p1);
            unpack_f32x2(acc[t][1], p2, p3);
            *(float4*)&tap[(c * 8 + t) * 68 + pb] = make_float4(p0, p1, p2, p3);
        }
    }

    __syncthreads();

    // ---------- Phase B: y[64o x 64p] = W[64 x 256] * tap[256 x 64] ----------
    // warp = 8 o-groups x 4 p-groups (minimizes smem bytes per warp per k)
    const int og  = (tid & 7) | (((tid >> 5) & 3) << 3);   // 0..31
    const int pgl = ((tid >> 3) & 3) | (((tid >> 7) & 7) << 2); // 0..15
    const int o_base = og << 1;    // 2 outputs
    const int pb     = pgl << 2;   // 4 points

    uint64_t acc00 = 0ull, acc01 = 0ull, acc10 = 0ull, acc11 = 0ull;

    const float* wsp = &ws[o_base];
    const uint64_t* tapp = (const uint64_t*)&tap[pb];

    #pragma unroll 8
    for (int k = 0; k < 256; k++) {
        float2 wv = *(const float2*)(wsp + k * 66);
        uint64_t t0 = tapp[k * 34 + 0];
        uint64_t t1 = tapp[k * 34 + 1];
        uint64_t aw0 = dup_f32x2(wv.x);
        uint64_t aw1 = dup_f32x2(wv.y);
        ffma2(acc00, aw0, t0);  ffma2(acc01, aw0, t1);
        ffma2(acc10, aw1, t0);  ffma2(acc11, aw1, t1);
    }

    // ---------- epilogue: + bias, float4 stores ----------
    {
        const size_t base = (((size_t)b * COUT) * DDIM + d0) * (HDIM * WDIM)
                          + (size_t)h0 * WDIM + pb;
        float bv0 = __ldg(&bias[o_base]);
        float bv1 = __ldg(&bias[o_base + 1]);
        float p0, p1, p2, p3;

        unpack_f32x2(acc00, p0, p1);
        unpack_f32x2(acc01, p2, p3);
        *(float4*)&out[base + (size_t)o_base * DDIM * HDIM * WDIM] =
            make_float4(p0 + bv0, p1 + bv0, p2 + bv0, p3 + bv0);

        unpack_f32x2(acc10, p0, p1);
        unpack_f32x2(acc11, p2, p3);
        *(float4*)&out[base + (size_t)(o_base + 1) * DDIM * HDIM * WDIM] =
            make_float4(p0 + bv1, p1 + bv1, p2 + bv1, p3 + bv1);
    }
}

extern "C" void kernel_launch(void* const* d_in, const int* in_sizes, int n_in,
                              void* d_out, int out_size) {
    const float* x        = (const float*)d_in[0];
    const float* stencils = (const float*)d_in[1];
    const float* weight   = (const float*)d_in[2];
    const float* bias     = (const float*)d_in[3];
    float* out = (float*)d_out;

    cudaFuncSetAttribute(stencilconv3d_kernel,
                         cudaFuncAttributeMaxDynamicSharedMemorySize, SMEM_BYTES);
    dim3 grid(HDIM, DDIM, BDIM);   // 64 x 32 x 4 = 8192 blocks
    stencilconv3d_kernel<<<grid, 512, SMEM_BYTES>>>(x, stencils, weight, bias, out);
}